// round 5
// baseline (speedup 1.0000x reference)
#include <cuda_runtime.h>
#include <cstdint>

// BaseEncoder: out[b, f, c] = (bitcast<u32>(x[b,f]) >> (31 - c)) & 1  (float),
// c = 0..31.  c==0 is bit 31 = sign bit (== (x<0) channel of the reference);
// c>=1 are bits 30..0 of |x| (abs only clears bit 31).
//
// Mapping: thread handles one output float4 (channels 4j..4j+3 of one input
// element). 8 consecutive lanes share one input word (broadcast LDG), stores
// are fully coalesced STG.128 — 512 contiguous bytes per warp per store.
// Pure HBM-write-bound: 256 MiB out @ ~8 TB/s ⇒ ~34 us floor.

__global__ void __launch_bounds__(256)
base_encoder_kernel(const uint32_t* __restrict__ x,
                    float4* __restrict__ out,
                    int n4)  // n4 = total output floats / 4
{
    const uint32_t ONE = 0x3f800000u;  // bit pattern of 1.0f
    int stride = gridDim.x * blockDim.x;

    for (int t = blockIdx.x * blockDim.x + threadIdx.x; t < n4; t += stride) {
        uint32_t u = x[t >> 3];      // input element index = (4*t)/32 = t/8
        int c0 = (t & 7) * 4;        // first bit-channel of this float4

        float4 v;
        v.x = __uint_as_float(((u >> (31 - c0)) & 1u) * ONE);
        v.y = __uint_as_float(((u >> (30 - c0)) & 1u) * ONE);
        v.z = __uint_as_float(((u >> (29 - c0)) & 1u) * ONE);
        v.w = __uint_as_float(((u >> (28 - c0)) & 1u) * ONE);

        out[t] = v;
    }
}

extern "C" void kernel_launch(void* const* d_in, const int* in_sizes, int n_in,
                              void* d_out, int out_size)
{
    const uint32_t* x = (const uint32_t*)d_in[0];
    float4* out = (float4*)d_out;

    int n4 = out_size / 4;           // 4096*512*32/4 = 16,777,216

    // 2 float4-iterations per thread per wave keeps the grid modest while
    // saturating all SMs: 148 SMs * up to 32 resident warps.
    int threads = 256;
    int blocks = (n4 + threads * 2 - 1) / (threads * 2);

    base_encoder_kernel<<<blocks, threads>>>(x, out, n4);
}